// round 2
// baseline (speedup 1.0000x reference)
#include <cuda_runtime.h>
#include <math.h>
#include <float.h>

#define BATCH 8
#define CH    256
#define NH    9
#define S     48
#define SP    (S*S)        // 2304
#define HD    (NH*CH)      // 2304
#define NSPAT (BATCH*SP)   // 18432

// Scratch (static __device__ — no allocations allowed)
__device__ float d_g1 [NH][S][S];   // [h][i][k]  normalized row softmax over k
__device__ float d_g2 [NH][S][S];   // [h][j][l]
__device__ float d_g1t[NH][S][S];   // [h][k][i]
__device__ float d_g2t[NH][S][S];   // [h][l][j]
__device__ float d_T[BATCH][CH][NH][S][S];  // [b][d][h][j][k]   (~170 MB)
__device__ float d_U[HD][NSPAT];            // [h*256+d][b*2304 + j*48 + i] (~170 MB)

// ---------------------------------------------------------------------------
// Kernel 0: per-row 1D Gaussian softmax factors (and transposes)
// ---------------------------------------------------------------------------
__global__ void k_gauss(const float* __restrict__ centers,
                        const float* __restrict__ spreads) {
    int gw   = (blockIdx.x * blockDim.x + threadIdx.x) >> 5;
    int lane = threadIdx.x & 31;
    if (gw >= 2 * NH * S) return;
    int which = gw / (NH * S);       // 0 -> P1 (mu1), 1 -> P2 (mu2)
    int r     = gw % (NH * S);
    int h = r / S, pos = r % S;      // pos = i (which=0) or j (which=1)
    float sp = spreads[h];
    float a  = sp * sp;
    float mu = centers[2 * h + which];

    float dx0 = (float)(lane - pos);
    float e0  = a * (mu * dx0 - 0.5f * dx0 * dx0);
    float e1  = -FLT_MAX;
    if (lane < S - 32) {
        float dx1 = (float)(lane + 32 - pos);
        e1 = a * (mu * dx1 - 0.5f * dx1 * dx1);
    }
    float m = fmaxf(e0, e1);
    #pragma unroll
    for (int o = 16; o > 0; o >>= 1) m = fmaxf(m, __shfl_xor_sync(0xffffffffu, m, o));
    float v0 = expf(e0 - m);
    float v1 = (lane < S - 32) ? expf(e1 - m) : 0.f;
    float s = v0 + v1;
    #pragma unroll
    for (int o = 16; o > 0; o >>= 1) s += __shfl_xor_sync(0xffffffffu, s, o);
    float inv = 1.f / s;
    v0 *= inv; v1 *= inv;

    float (*g )[S] = which ? d_g2 [h] : d_g1 [h];
    float (*gt)[S] = which ? d_g2t[h] : d_g1t[h];
    g [pos][lane] = v0;
    gt[lane][pos] = v0;
    if (lane < S - 32) {
        g [pos][lane + 32] = v1;
        gt[lane + 32][pos] = v1;
    }
}

// ---------------------------------------------------------------------------
// Kernel 1: probs[i,j,h,k,l] = P1[h,i,k] * P2[h,j,l]   (pure HBM write)
// blockIdx.x = (i*48 + j)*9 + h  -> matches probs flattening exactly
// ---------------------------------------------------------------------------
__global__ __launch_bounds__(192) void k_probs(float* __restrict__ probs) {
    int blk = blockIdx.x;
    int h   = blk % NH;
    int ij  = blk / NH;
    int j = ij % S, i = ij / S;
    __shared__ float f[S];
    __shared__ float g[S];
    int t = threadIdx.x;
    if (t < S)            f[t]     = d_g1[h][i][t];
    else if (t < 2 * S)   g[t - S] = d_g2[h][j][t - S];
    __syncthreads();
    float4* outp = (float4*)(probs + (size_t)blk * SP);
    const float4* g4 = (const float4*)g;
    #pragma unroll
    for (int q = t; q < SP / 4; q += 192) {
        int k = q / 12, l4 = q % 12;
        float  fk = f[k];
        float4 gv = g4[l4];
        outp[q] = make_float4(fk * gv.x, fk * gv.y, fk * gv.z, fk * gv.w);
    }
}

// ---------------------------------------------------------------------------
// Kernel 2 (stage A): T[b,d,h,j,k] = sum_l P2[h,j,l] * hs[b,d,l,k]
// One block = (b, d-pair); 288 thr = 2 slabs x 144 (12x12 thread grid, 4x4 tiles)
// ---------------------------------------------------------------------------
__global__ __launch_bounds__(288) void k_stageA(const float* __restrict__ hs) {
    __shared__ float Xs[2][SP];   // [slab][l*48 + k]
    __shared__ float Gt[SP];      // [l*48 + j]
    int blk = blockIdx.x;
    int b  = blk >> 7;
    int dp = blk & 127;
    int t  = threadIdx.x;
    int slab = t / 144, tt = t % 144;
    int tk = tt % 12, tj = tt / 12;
    {
        const float4* src = (const float4*)(hs + (size_t)(b * CH + dp * 2) * SP);
        float4* dst = (float4*)&Xs[0][0];
        for (int q = t; q < 2 * SP / 4; q += 288) dst[q] = src[q];
    }
    for (int h = 0; h < NH; h++) {
        __syncthreads();
        {
            const float4* gsrc = (const float4*)&d_g2t[h][0][0];
            float4* gdst = (float4*)Gt;
            for (int q = t; q < SP / 4; q += 288) gdst[q] = gsrc[q];
        }
        __syncthreads();
        float acc[4][4];
        #pragma unroll
        for (int jj = 0; jj < 4; jj++)
            #pragma unroll
            for (int kk = 0; kk < 4; kk++) acc[jj][kk] = 0.f;
        const float* X = Xs[slab];
        #pragma unroll 8
        for (int l = 0; l < S; l++) {
            float4 xv = ((const float4*)(X  + l * S))[tk];
            float4 gv = ((const float4*)(Gt + l * S))[tj];
            float xa[4] = {xv.x, xv.y, xv.z, xv.w};
            float ga[4] = {gv.x, gv.y, gv.z, gv.w};
            #pragma unroll
            for (int jj = 0; jj < 4; jj++)
                #pragma unroll
                for (int kk = 0; kk < 4; kk++)
                    acc[jj][kk] = fmaf(ga[jj], xa[kk], acc[jj][kk]);
        }
        float* Tb = &d_T[b][dp * 2 + slab][h][0][0];
        #pragma unroll
        for (int jj = 0; jj < 4; jj++) {
            float4 v = make_float4(acc[jj][0], acc[jj][1], acc[jj][2], acc[jj][3]);
            ((float4*)(Tb + (tj * 4 + jj) * S))[tk] = v;
        }
    }
}

// ---------------------------------------------------------------------------
// Kernel 3 (stage B): U[h*256+d][b*2304 + j*48 + i] = sum_k P1[h,i,k]*T[b,d,h,j,k]
// ---------------------------------------------------------------------------
__global__ __launch_bounds__(288) void k_stageB() {
    __shared__ float Ts[2][SP];   // [slab][k*48 + j]  (transposed on load)
    __shared__ float G1s[SP];     // [k*48 + i]
    int blk = blockIdx.x;
    int b  = blk >> 7;
    int dp = blk & 127;
    int t  = threadIdx.x;
    int slab = t / 144, tt = t % 144;
    int ti = tt % 12, tj = tt / 12;
    for (int h = 0; h < NH; h++) {
        __syncthreads();
        {
            const float4* gsrc = (const float4*)&d_g1t[h][0][0];
            float4* gdst = (float4*)G1s;
            for (int q = t; q < SP / 4; q += 288) gdst[q] = gsrc[q];
            for (int q = t; q < 2 * SP / 4; q += 288) {
                int sq = q / 576, qi = q % 576;
                int j = qi / 12, k4 = qi % 12;
                float4 v = ((const float4*)&d_T[b][dp * 2 + sq][h][j][0])[k4];
                float* ts = Ts[sq];
                ts[(k4 * 4 + 0) * S + j] = v.x;
                ts[(k4 * 4 + 1) * S + j] = v.y;
                ts[(k4 * 4 + 2) * S + j] = v.z;
                ts[(k4 * 4 + 3) * S + j] = v.w;
            }
        }
        __syncthreads();
        float acc[4][4];
        #pragma unroll
        for (int jj = 0; jj < 4; jj++)
            #pragma unroll
            for (int ii = 0; ii < 4; ii++) acc[jj][ii] = 0.f;
        const float* T2 = Ts[slab];
        #pragma unroll 8
        for (int k = 0; k < S; k++) {
            float4 iv = ((const float4*)(G1s + k * S))[ti];
            float4 jv = ((const float4*)(T2  + k * S))[tj];
            float ia[4] = {iv.x, iv.y, iv.z, iv.w};
            float ja[4] = {jv.x, jv.y, jv.z, jv.w};
            #pragma unroll
            for (int jj = 0; jj < 4; jj++)
                #pragma unroll
                for (int ii = 0; ii < 4; ii++)
                    acc[jj][ii] = fmaf(ja[jj], ia[ii], acc[jj][ii]);
        }
        float* Ub = &d_U[h * CH + dp * 2 + slab][(size_t)b * SP];
        #pragma unroll
        for (int jj = 0; jj < 4; jj++) {
            float4 v = make_float4(acc[jj][0], acc[jj][1], acc[jj][2], acc[jj][3]);
            ((float4*)(Ub + (tj * 4 + jj) * S))[ti] = v;
        }
    }
}

// ---------------------------------------------------------------------------
// Kernel 4 (stage C): out[b,c,j,i] = bias[c] + sum_hd W[c][hd] * U[hd][spat]
// GEMM: M=256 (c), N=18432 (spat = b*2304 + j*48 + i), K=2304.
// 128x128x16 tile, 8x8 per thread with split fragments (conflict-free LDS.128).
// ---------------------------------------------------------------------------
#define BK 16
__global__ __launch_bounds__(256) void k_stageC(const float* __restrict__ W,
                                                const float* __restrict__ bias,
                                                float* __restrict__ out) {
    __shared__ float Ws[BK][128];   // [p][c]   (transposed from W)
    __shared__ float Us[BK][128];   // [p][s]
    int s0 = blockIdx.x * 128;
    int c0 = blockIdx.y * 128;
    int t  = threadIdx.x;
    int tc = t & 15, ts = t >> 4;
    float acc[8][8];
    #pragma unroll
    for (int r = 0; r < 8; r++)
        #pragma unroll
        for (int u = 0; u < 8; u++) acc[r][u] = 0.f;

    const float4* W4     = (const float4*)W;
    const float4* U4base = (const float4*)&d_U[0][0];

    for (int p0 = 0; p0 < HD; p0 += BK) {
        __syncthreads();
        #pragma unroll
        for (int q = t; q < 512; q += 256) {
            int c = q >> 2, p4 = q & 3;
            float4 v = W4[(size_t)(c0 + c) * (HD / 4) + (p0 >> 2) + p4];
            Ws[p4 * 4 + 0][c] = v.x;
            Ws[p4 * 4 + 1][c] = v.y;
            Ws[p4 * 4 + 2][c] = v.z;
            Ws[p4 * 4 + 3][c] = v.w;
        }
        #pragma unroll
        for (int q = t; q < 512; q += 256) {
            int k = q >> 5, s4 = q & 31;
            ((float4*)Us[k])[s4] = U4base[(size_t)(p0 + k) * (NSPAT / 4) + (s0 >> 2) + s4];
        }
        __syncthreads();
        #pragma unroll
        for (int k = 0; k < BK; k++) {
            float4 a0 = ((const float4*)Ws[k])[tc];
            float4 a1 = ((const float4*)Ws[k])[16 + tc];
            float4 b0 = ((const float4*)Us[k])[ts];
            float4 b1 = ((const float4*)Us[k])[16 + ts];
            float av[8] = {a0.x, a0.y, a0.z, a0.w, a1.x, a1.y, a1.z, a1.w};
            float bv[8] = {b0.x, b0.y, b0.z, b0.w, b1.x, b1.y, b1.z, b1.w};
            #pragma unroll
            for (int r = 0; r < 8; r++)
                #pragma unroll
                for (int u = 0; u < 8; u++)
                    acc[r][u] = fmaf(av[r], bv[u], acc[r][u]);
        }
    }

    int b   = s0 / SP;      // tile never crosses batch (2304 = 18*128)
    int sp0 = s0 % SP;
    #pragma unroll
    for (int r = 0; r < 8; r++) {
        int c = c0 + (r >> 2) * 64 + tc * 4 + (r & 3);
        float bvl = bias[c];
        float* op = out + ((size_t)(b * CH + c)) * SP + sp0;
        #pragma unroll
        for (int sh = 0; sh < 2; sh++) {
            int sb = sh * 64 + ts * 4;
            float4 v = make_float4(acc[r][sh * 4 + 0] + bvl,
                                   acc[r][sh * 4 + 1] + bvl,
                                   acc[r][sh * 4 + 2] + bvl,
                                   acc[r][sh * 4 + 3] + bvl);
            *(float4*)(op + sb) = v;
        }
    }
}

// ---------------------------------------------------------------------------
extern "C" void kernel_launch(void* const* d_in, const int* in_sizes, int n_in,
                              void* d_out, int out_size) {
    const float* hs      = (const float*)d_in[0];
    const float* centers = (const float*)d_in[1];
    const float* spreads = (const float*)d_in[2];
    const float* W       = (const float*)d_in[3];
    const float* bias    = (const float*)d_in[4];
    float* out   = (float*)d_out;
    float* probs = out + (size_t)BATCH * CH * SP;   // out first, then probs

    k_gauss <<<(2 * NH * S + 3) / 4, 128>>>(centers, spreads);
    k_probs <<<SP * NH, 192>>>(probs);
    k_stageA<<<BATCH * (CH / 2), 288>>>(hs);
    k_stageB<<<BATCH * (CH / 2), 288>>>();
    k_stageC<<<dim3(NSPAT / 128, CH / 128), 256>>>(W, bias, out);
    (void)in_sizes; (void)n_in; (void)out_size;
}

// round 4
// speedup vs baseline: 1.1084x; 1.1084x over previous
#include <cuda_runtime.h>
#include <math.h>
#include <float.h>
#include <stdint.h>

#define BATCH 8
#define CH    256
#define NH    9
#define S     48
#define SP    (S*S)        // 2304
#define HD    (NH*CH)      // 2304
#define NSPAT (BATCH*SP)   // 18432

typedef unsigned long long ull;

// f32x2 packed helpers (family-wide PTX feature, works on .target sm_103)
#define FMA2(d,a,b)  asm("fma.rn.f32x2 %0, %1, %2, %0;" : "+l"(d) : "l"(a), "l"(b))
#define PACK2(d,x,y) asm("mov.b64 %0, {%1,%2};" : "=l"(d) : "f"(x), "f"(y))
#define DUP2(d,x)    asm("mov.b64 %0, {%1,%1};" : "=l"(d) : "f"(x))
#define UNPK2(x,y,d) asm("mov.b64 {%0,%1}, %2;" : "=f"(x), "=f"(y) : "l"(d))

// Scratch (static __device__ — no allocations allowed)
__device__ float d_g1 [NH][S][S];   // [h][i][k]
__device__ float d_g2 [NH][S][S];   // [h][j][l]
__device__ float d_g1t[NH][S][S];   // [h][k][i]
__device__ float d_g2t[NH][S][S];   // [h][l][j]
__device__ float d_U[HD][NSPAT];    // [hd][b*2304 + j*48 + i]

// ---------------------------------------------------------------------------
// Kernel 0: per-row 1D Gaussian softmax factors (and transposes)
// ---------------------------------------------------------------------------
__global__ void k_gauss(const float* __restrict__ centers,
                        const float* __restrict__ spreads) {
    int gw   = (blockIdx.x * blockDim.x + threadIdx.x) >> 5;
    int lane = threadIdx.x & 31;
    if (gw >= 2 * NH * S) return;
    int which = gw / (NH * S);
    int r     = gw % (NH * S);
    int h = r / S, pos = r % S;
    float sp = spreads[h];
    float a  = sp * sp;
    float mu = centers[2 * h + which];

    float dx0 = (float)(lane - pos);
    float e0  = a * (mu * dx0 - 0.5f * dx0 * dx0);
    float e1  = -FLT_MAX;
    if (lane < S - 32) {
        float dx1 = (float)(lane + 32 - pos);
        e1 = a * (mu * dx1 - 0.5f * dx1 * dx1);
    }
    float m = fmaxf(e0, e1);
    #pragma unroll
    for (int o = 16; o > 0; o >>= 1) m = fmaxf(m, __shfl_xor_sync(0xffffffffu, m, o));
    float v0 = expf(e0 - m);
    float v1 = (lane < S - 32) ? expf(e1 - m) : 0.f;
    float s = v0 + v1;
    #pragma unroll
    for (int o = 16; o > 0; o >>= 1) s += __shfl_xor_sync(0xffffffffu, s, o);
    float inv = 1.f / s;
    v0 *= inv; v1 *= inv;

    float (*g )[S] = which ? d_g2 [h] : d_g1 [h];
    float (*gt)[S] = which ? d_g2t[h] : d_g1t[h];
    g [pos][lane] = v0;
    gt[lane][pos] = v0;
    if (lane < S - 32) {
        g [pos][lane + 32] = v1;
        gt[lane + 32][pos] = v1;
    }
}

// ---------------------------------------------------------------------------
// Kernel 1: probs[i,j,h,k,l] = P1[h,i,k] * P2[h,j,l]   (pure HBM write)
// ---------------------------------------------------------------------------
__global__ __launch_bounds__(192) void k_probs(float* __restrict__ probs) {
    int blk = blockIdx.x;
    int h   = blk % NH;
    int ij  = blk / NH;
    int j = ij % S, i = ij / S;
    __shared__ float f[S];
    __shared__ float g[S];
    int t = threadIdx.x;
    if (t < S)            f[t]     = d_g1[h][i][t];
    else if (t < 2 * S)   g[t - S] = d_g2[h][j][t - S];
    __syncthreads();
    float4* outp = (float4*)(probs + (size_t)blk * SP);
    const float4* g4 = (const float4*)g;
    #pragma unroll
    for (int q = t; q < SP / 4; q += 192) {
        int k = q / 12, l4 = q % 12;
        float  fk = f[k];
        float4 gv = g4[l4];
        outp[q] = make_float4(fk * gv.x, fk * gv.y, fk * gv.z, fk * gv.w);
    }
}

// ---------------------------------------------------------------------------
// Fused stages A+B (per block: one (b, d-pair); T kept in smem):
//   T[j,k] = sum_l P2[h,j,l] * X[l,k]
//   U[h*256+d][b*2304 + j*48 + i] = sum_k P1[h,i,k] * T[j,k]
// 288 thr = 2 slabs x 144 (12x12 thread grid, 4x4 tiles). f32x2 inner loops.
// ---------------------------------------------------------------------------
__global__ __launch_bounds__(288) void k_fusedAB(const float* __restrict__ hs) {
    __shared__ float Xs[2][SP];   // [slab][l*48 + k]
    __shared__ float Ts[2][SP];   // [slab][j*48 + k]
    __shared__ float Gs[SP];      // g2t[l*48+j] then g1t[k*48+i]
    int blk = blockIdx.x;
    int b  = blk >> 7;
    int dp = blk & 127;
    int t  = threadIdx.x;
    int slab = t / 144, tt = t % 144;
    int tk = tt % 12, tj = tt / 12;
    {
        const float4* src = (const float4*)(hs + (size_t)(b * CH + dp * 2) * SP);
        float4* dst = (float4*)&Xs[0][0];
        for (int q = t; q < 2 * SP / 4; q += 288) dst[q] = src[q];
    }
    for (int h = 0; h < NH; h++) {
        __syncthreads();   // prior-h stage2 done reading Ts/Gs
        {
            const float4* gsrc = (const float4*)&d_g2t[h][0][0];
            float4* gdst = (float4*)Gs;
            for (int q = t; q < SP / 4; q += 288) gdst[q] = gsrc[q];
        }
        __syncthreads();
        // ---- stage 1: T = P2 * X  (acc pairs along k) ----
        ull acc1[4][2];
        #pragma unroll
        for (int jj = 0; jj < 4; jj++) { acc1[jj][0] = 0ull; acc1[jj][1] = 0ull; }
        const float* X = Xs[slab];
        #pragma unroll 4
        for (int l = 0; l < S; l++) {
            float4 xv = ((const float4*)(X  + l * S))[tk];
            float4 gv = ((const float4*)(Gs + l * S))[tj];
            ull xp0, xp1;
            PACK2(xp0, xv.x, xv.y);
            PACK2(xp1, xv.z, xv.w);
            float ga[4] = {gv.x, gv.y, gv.z, gv.w};
            #pragma unroll
            for (int jj = 0; jj < 4; jj++) {
                ull gd; DUP2(gd, ga[jj]);
                FMA2(acc1[jj][0], gd, xp0);
                FMA2(acc1[jj][1], gd, xp1);
            }
        }
        __syncthreads();   // stage1 reads of Gs complete before Gs reload
        // write T tile (row-major [j][k]) + load g1t
        #pragma unroll
        for (int jj = 0; jj < 4; jj++) {
            float x0, x1, x2, x3;
            UNPK2(x0, x1, acc1[jj][0]);
            UNPK2(x2, x3, acc1[jj][1]);
            ((float4*)(Ts[slab] + (tj * 4 + jj) * S))[tk] = make_float4(x0, x1, x2, x3);
        }
        {
            const float4* gsrc = (const float4*)&d_g1t[h][0][0];
            float4* gdst = (float4*)Gs;
            for (int q = t; q < SP / 4; q += 288) gdst[q] = gsrc[q];
        }
        __syncthreads();
        // ---- stage 2: U = T * P1^T  (acc pairs along i; T broadcast scalar) ----
        ull acc2[4][2];
        #pragma unroll
        for (int jj = 0; jj < 4; jj++) { acc2[jj][0] = 0ull; acc2[jj][1] = 0ull; }
        const float* T2 = Ts[slab];
        #pragma unroll 2
        for (int k4 = 0; k4 < S / 4; k4++) {
            float tvf[4][4];
            #pragma unroll
            for (int jj = 0; jj < 4; jj++) {
                float4 tv = *(const float4*)(T2 + (tj * 4 + jj) * S + k4 * 4);
                tvf[jj][0] = tv.x; tvf[jj][1] = tv.y; tvf[jj][2] = tv.z; tvf[jj][3] = tv.w;
            }
            #pragma unroll
            for (int kk = 0; kk < 4; kk++) {
                float4 iv = ((const float4*)(Gs + (k4 * 4 + kk) * S))[tk];
                ull ip0, ip1;
                PACK2(ip0, iv.x, iv.y);
                PACK2(ip1, iv.z, iv.w);
                #pragma unroll
                for (int jj = 0; jj < 4; jj++) {
                    ull td; DUP2(td, tvf[jj][kk]);
                    FMA2(acc2[jj][0], td, ip0);
                    FMA2(acc2[jj][1], td, ip1);
                }
            }
        }
        float* Ub = &d_U[h * CH + dp * 2 + slab][(size_t)b * SP];
        #pragma unroll
        for (int jj = 0; jj < 4; jj++) {
            float x0, x1, x2, x3;
            UNPK2(x0, x1, acc2[jj][0]);
            UNPK2(x2, x3, acc2[jj][1]);
            ((float4*)(Ub + (tj * 4 + jj) * S))[tk] = make_float4(x0, x1, x2, x3);
        }
    }
}

// ---------------------------------------------------------------------------
// Stage C: out[b,c,j,i] = bias[c] + sum_hd W[c][hd] * U[hd][spat]
// GEMM M=256, N=18432, K=2304. 128x128x16 tile, 8x8 per thread, f32x2 FFMA2.
// ---------------------------------------------------------------------------
#define BK 16
__global__ __launch_bounds__(256) void k_stageC(const float* __restrict__ W,
                                                const float* __restrict__ bias,
                                                float* __restrict__ out) {
    __shared__ float Ws[BK][128];   // [p][c]
    __shared__ float Us[BK][128];   // [p][s]
    int s0 = blockIdx.x * 128;
    int c0 = blockIdx.y * 128;
    int t  = threadIdx.x;
    int tc = t & 15, ts = t >> 4;
    ull acc2[8][4];
    #pragma unroll
    for (int r = 0; r < 8; r++)
        #pragma unroll
        for (int u = 0; u < 4; u++) acc2[r][u] = 0ull;

    const float4* W4     = (const float4*)W;
    const float4* U4base = (const float4*)&d_U[0][0];

    for (int p0 = 0; p0 < HD; p0 += BK) {
        __syncthreads();
        #pragma unroll
        for (int q = t; q < 512; q += 256) {
            int c = q >> 2, p4 = q & 3;
            float4 v = W4[(size_t)(c0 + c) * (HD / 4) + (p0 >> 2) + p4];
            Ws[p4 * 4 + 0][c] = v.x;
            Ws[p4 * 4 + 1][c] = v.y;
            Ws[p4 * 4 + 2][c] = v.z;
            Ws[p4 * 4 + 3][c] = v.w;
        }
        #pragma unroll
        for (int q = t; q < 512; q += 256) {
            int k = q >> 5, s4 = q & 31;
            ((float4*)Us[k])[s4] = U4base[(size_t)(p0 + k) * (NSPAT / 4) + (s0 >> 2) + s4];
        }
        __syncthreads();
        #pragma unroll
        for (int k = 0; k < BK; k++) {
            float4 a0 = ((const float4*)Ws[k])[tc];
            float4 a1 = ((const float4*)Ws[k])[16 + tc];
            float4 b0 = ((const float4*)Us[k])[ts];
            float4 b1 = ((const float4*)Us[k])[16 + ts];
            ull bp0, bp1, bp2, bp3;
            PACK2(bp0, b0.x, b0.y);
            PACK2(bp1, b0.z, b0.w);
            PACK2(bp2, b1.x, b1.y);
            PACK2(bp3, b1.z, b1.w);
            float av[8] = {a0.x, a0.y, a0.z, a0.w, a1.x, a1.y, a1.z, a1.w};
            #pragma unroll
            for (int r = 0; r < 8; r++) {
                ull ad; DUP2(ad, av[r]);
                FMA2(acc2[r][0], ad, bp0);
                FMA2(acc2[r][1], ad, bp1);
                FMA2(acc2[r][2], ad, bp2);
                FMA2(acc2[r][3], ad, bp3);
            }
        }
    }

    int b   = s0 / SP;      // tile never crosses batch (2304 = 18*128)
    int sp0 = s0 % SP;
    #pragma unroll
    for (int r = 0; r < 8; r++) {
        int c = c0 + (r >> 2) * 64 + tc * 4 + (r & 3);
        float bvl = bias[c];
        float* op = out + ((size_t)(b * CH + c)) * SP + sp0;
        #pragma unroll
        for (int sh = 0; sh < 2; sh++) {
            float x0, x1, x2, x3;
            UNPK2(x0, x1, acc2[r][sh * 2 + 0]);
            UNPK2(x2, x3, acc2[r][sh * 2 + 1]);
            int sb = sh * 64 + ts * 4;
            *(float4*)(op + sb) = make_float4(x0 + bvl, x1 + bvl, x2 + bvl, x3 + bvl);
        }
    }
}

// ---------------------------------------------------------------------------
extern "C" void kernel_launch(void* const* d_in, const int* in_sizes, int n_in,
                              void* d_out, int out_size) {
    const float* hs      = (const float*)d_in[0];
    const float* centers = (const float*)d_in[1];
    const float* spreads = (const float*)d_in[2];
    const float* W       = (const float*)d_in[3];
    const float* bias    = (const float*)d_in[4];
    float* out   = (float*)d_out;
    float* probs = out + (size_t)BATCH * CH * SP;

    k_gauss  <<<(2 * NH * S + 3) / 4, 128>>>(centers, spreads);
    k_probs  <<<SP * NH, 192>>>(probs);
    k_fusedAB<<<BATCH * (CH / 2), 288>>>(hs);
    k_stageC <<<dim3(NSPAT / 128, CH / 128), 256>>>(W, bias, out);
    (void)in_sizes; (void)n_in; (void)out_size;
}